// round 7
// baseline (speedup 1.0000x reference)
#include <cuda_runtime.h>
#include <cuda_fp16.h>
#include <cstdint>

#define K_DIM 1024
#define M_DIM 2048
#define N_DIM 1024
#define NCHUNK 64
#define NITER  16   // 4 chunks per iteration

// fp16 split planes, 64 B per row: A=[hi(32B)|lo(32B)], B=[whi(32B)|wlo(32B)]
__device__ __half g_A[(size_t)NCHUNK * M_DIM * 32];
__device__ __half g_B[(size_t)NCHUNK * N_DIM * 32];

// ---------------------------------------------------------------------------
// Fused prep: blocks [0,512) do X, [512,768) do W. LUTs staged in smem.
// ---------------------------------------------------------------------------
__global__ void prep_kernel(const float* __restrict__ X,
                            const float* __restrict__ W,
                            const float* __restrict__ vmap,
                            const float* __restrict__ wmap) {
    __shared__ float s_lut[256];
    const bool isX = blockIdx.x < 512;
    s_lut[threadIdx.x] = isX ? vmap[threadIdx.x] : wmap[threadIdx.x];
    __syncthreads();

    if (isX) {
        int gid = blockIdx.x * 256 + threadIdx.x;
        int r = gid >> 11, m = gid & 2047;
        const float* src = X + (size_t)m * K_DIM + r * 16;
        float xs[16];
        ((float4*)xs)[0] = ((const float4*)src)[0];
        ((float4*)xs)[1] = ((const float4*)src)[1];
        ((float4*)xs)[2] = ((const float4*)src)[2];
        ((float4*)xs)[3] = ((const float4*)src)[3];
        unsigned hi[8], lo[8];
#pragma unroll
        for (int jj = 0; jj < 8; jj++) {
            unsigned short h[2], l[2];
#pragma unroll
            for (int e = 0; e < 2; e++) {
                int j = 2 * jj + e;
                float xv = xs[j];
                int idx = (int)(xv + 8.0f);
                idx = idx < 0 ? 0 : (idx > 15 ? 15 : idx);
                float xc = (xv + s_lut[j * 16 + idx]) * 0.0625f;
                __half hh = __float2half_rn(xc);
                __half ll = __float2half_rn(xc - __half2float(hh));
                h[e] = __half_as_ushort(hh);
                l[e] = __half_as_ushort(ll);
            }
            hi[jj] = h[0] | ((unsigned)h[1] << 16);
            lo[jj] = l[0] | ((unsigned)l[1] << 16);
        }
        uint4* dst = (uint4*)(g_A + ((size_t)r * M_DIM + m) * 32);
        dst[0] = make_uint4(hi[0], hi[1], hi[2], hi[3]);
        dst[1] = make_uint4(hi[4], hi[5], hi[6], hi[7]);
        dst[2] = make_uint4(lo[0], lo[1], lo[2], lo[3]);
        dst[3] = make_uint4(lo[4], lo[5], lo[6], lo[7]);
    } else {
        int idx4 = blockIdx.x - 512;
        int r = idx4 >> 2;
        int n = (idx4 & 3) * 256 + threadIdx.x;
        unsigned hi[8], lo[8];
#pragma unroll
        for (int jj = 0; jj < 8; jj++) {
            unsigned short h[2], l[2];
#pragma unroll
            for (int e = 0; e < 2; e++) {
                int j = 2 * jj + e;
                float w = W[(size_t)(16 * r + j) * N_DIM + n];
                int idx = (int)(w + 8.0f);
                idx = idx < 0 ? 0 : (idx > 15 ? 15 : idx);
                float wc = w + s_lut[j * 16 + idx];
                __half hh = __float2half_rn(wc);
                __half ll = __float2half_rn(wc - __half2float(hh));
                h[e] = __half_as_ushort(hh);
                l[e] = __half_as_ushort(ll);
            }
            hi[jj] = h[0] | ((unsigned)h[1] << 16);
            lo[jj] = l[0] | ((unsigned)l[1] << 16);
        }
        uint4* dst = (uint4*)(g_B + ((size_t)r * N_DIM + n) * 32);
        dst[0] = make_uint4(hi[0], hi[1], hi[2], hi[3]);
        dst[1] = make_uint4(hi[4], hi[5], hi[6], hi[7]);
        dst[2] = make_uint4(lo[0], lo[1], lo[2], lo[3]);
        dst[3] = make_uint4(lo[4], lo[5], lo[6], lo[7]);
    }
}

// ---------------------------------------------------------------------------
#define LDSM4(R, addr)                                                         \
    asm volatile("ldmatrix.sync.aligned.m8n8.x4.shared.b16 {%0,%1,%2,%3}, [%4];" \
                 : "=r"((R)[0]), "=r"((R)[1]), "=r"((R)[2]), "=r"((R)[3])      \
                 : "r"(addr))

#define MMA16816(C, A0, A1, A2, A3, B0, B1)                                    \
    asm volatile("mma.sync.aligned.m16n8k16.row.col.f32.f16.f16.f32 "          \
                 "{%0,%1,%2,%3}, {%4,%5,%6,%7}, {%8,%9}, {%0,%1,%2,%3};"       \
                 : "+f"((C)[0]), "+f"((C)[1]), "+f"((C)[2]), "+f"((C)[3])      \
                 : "r"(A0), "r"(A1), "r"(A2), "r"(A3), "r"(B0), "r"(B1))

// swizzled smem offset for (row, 16-B granule c in 0..3), 64-B logical rows
__device__ __forceinline__ unsigned phys(int row, int c) {
    return ((unsigned)(row >> 1) << 7) + ((unsigned)(row & 1) << 6) +
           (((unsigned)(c ^ ((row >> 1) & 3))) << 4);
}

// buffer layout: 4 chunks, each A 8K + B 4K = 12K; buffer = 48 KB
#define CH_BYTES  12288u
#define BUF_BYTES 49152u
#define A_OFF(c)  ((unsigned)(c) * CH_BYTES)
#define B_OFF(c)  ((unsigned)(c) * CH_BYTES + 8192u)

// ---------------------------------------------------------------------------
// Main: quad-chunk iterations, double-buffered, ONE syncthreads per 4 chunks.
// CTA tile 128m x 64n, 8 warps 4(m) x 2(n), warp tile 32m x 32n.
// grid (16,16), 2 CTA/SM, 96 KB dynamic smem.
// ---------------------------------------------------------------------------
__global__ void __launch_bounds__(256, 2)
opu_main_kernel(float* __restrict__ out) {
    extern __shared__ __align__(1024) char smem[];
    const unsigned sb0 = (unsigned)__cvta_generic_to_shared(smem);

    const int t = threadIdx.x, wid = t >> 5, lane = t & 31;
    const int m0 = blockIdx.x * 128, n0 = blockIdx.y * 64;
    const int wm = (wid >> 1) * 32, wn = (wid & 1) * 32;

    // staging: per chunk, A 512 granules (2/thread), B 256 granules (1/thread)
    const int ar0 = t >> 2, ac0 = t & 3;
    const int ar1 = (t + 256) >> 2;
    const unsigned adst0 = phys(ar0, ac0), adst1 = phys(ar1, ac0);
    const unsigned bdst = phys(ar0, ac0);

#define STAGE_ITER(i, s)                                                        \
    do {                                                                        \
        unsigned base = sb0 + (s) * BUF_BYTES;                                  \
        _Pragma("unroll")                                                       \
        for (int c = 0; c < 4; c++) {                                           \
            int ch = 4 * (i) + c;                                               \
            const void* s0 = g_A + ((size_t)ch * M_DIM + m0 + ar0) * 32 + ac0 * 8; \
            const void* s1 = g_A + ((size_t)ch * M_DIM + m0 + ar1) * 32 + ac0 * 8; \
            const void* s2 = g_B + ((size_t)ch * N_DIM + n0 + ar0) * 32 + ac0 * 8; \
            asm volatile("cp.async.cg.shared.global [%0], [%1], 16;" ::        \
                         "r"(base + A_OFF(c) + adst0), "l"(s0));               \
            asm volatile("cp.async.cg.shared.global [%0], [%1], 16;" ::        \
                         "r"(base + A_OFF(c) + adst1), "l"(s1));               \
            asm volatile("cp.async.cg.shared.global [%0], [%1], 16;" ::        \
                         "r"(base + B_OFF(c) + bdst), "l"(s2));                \
        }                                                                       \
        asm volatile("cp.async.commit_group;");                                 \
    } while (0)

    // ldmatrix addresses
    const int l15 = lane & 15, lhi = lane >> 4;
    const int l7 = lane & 7, lq = lane >> 3;
    unsigned ahi_ad[2], alo_ad[2], b_ad[4];
#pragma unroll
    for (int i = 0; i < 2; i++) {
        int row = wm + 16 * i + l15;
        ahi_ad[i] = phys(row, lhi);
        alo_ad[i] = phys(row, 2 + lhi);
    }
#pragma unroll
    for (int j = 0; j < 4; j++) {
        int row = wn + 8 * j + l7;
        b_ad[j] = phys(row, lq);
    }

    unsigned su[2][4][4];
#pragma unroll
    for (int i = 0; i < 2; i++)
#pragma unroll
        for (int j = 0; j < 4; j++)
#pragma unroll
            for (int e = 0; e < 4; e++) su[i][j][e] = 0u;

    STAGE_ITER(0, 0);

    for (int it = 0; it < NITER; it++) {
        asm volatile("cp.async.wait_group 0;" ::: "memory");
        __syncthreads();   // all copies of buf it&1 complete + all prior reads done

        if (it + 1 < NITER) STAGE_ITER(it + 1, (it + 1) & 1);

        const unsigned base = sb0 + (it & 1) * BUF_BYTES;

#pragma unroll
        for (int c = 0; c < 4; c++) {
            const unsigned ab = base + A_OFF(c);
            const unsigned bb = base + B_OFF(c);

            unsigned bfr[4][4], ah[2][4], al[2][4];
#pragma unroll
            for (int j = 0; j < 4; j++) LDSM4(bfr[j], bb + b_ad[j]);
#pragma unroll
            for (int i = 0; i < 2; i++) LDSM4(ah[i], ab + ahi_ad[i]);
#pragma unroll
            for (int i = 0; i < 2; i++) LDSM4(al[i], ab + alo_ad[i]);

            float acc[2][4][4];
#pragma unroll
            for (int i = 0; i < 2; i++)
#pragma unroll
                for (int j = 0; j < 4; j++)
#pragma unroll
                    for (int e = 0; e < 4; e++) acc[i][j][e] = 0.0f;

#pragma unroll
            for (int i = 0; i < 2; i++)
#pragma unroll
                for (int j = 0; j < 4; j++) {
                    MMA16816(acc[i][j], ah[i][0], ah[i][1], ah[i][2], ah[i][3],
                             bfr[j][0], bfr[j][1]);                  // hi*whi
                    MMA16816(acc[i][j], ah[i][0], ah[i][1], ah[i][2], ah[i][3],
                             bfr[j][2], bfr[j][3]);                  // hi*wlo
                    MMA16816(acc[i][j], al[i][0], al[i][1], al[i][2], al[i][3],
                             bfr[j][0], bfr[j][1]);                  // lo*whi
                }

            // ADC: acc = mm/16; +magic (1.5*2^23) -> RNE int in mantissa.
            // Clip never fires (|mm/16| <= 67 < 127.5).
#pragma unroll
            for (int i = 0; i < 2; i++)
#pragma unroll
                for (int j = 0; j < 4; j++)
#pragma unroll
                    for (int e = 0; e < 4; e++) {
                        float tt = acc[i][j][e] + 12582912.0f;
                        su[i][j][e] += __float_as_uint(tt);
                    }
        }
    }

    // out = 16 * (su - 64*0x4B400000 mod 2^32)
    const unsigned BIAS64 = 0xD0000000u;
    const int g = lane >> 2, tg = lane & 3;
#pragma unroll
    for (int i = 0; i < 2; i++)
#pragma unroll
        for (int h = 0; h < 2; h++) {
            int row = m0 + wm + 16 * i + 8 * h + g;
            float* orow = out + (size_t)row * N_DIM + n0 + wn + 2 * tg;
#pragma unroll
            for (int j = 0; j < 4; j++) {
                float2 o;
                o.x = 16.0f * (float)(int)(su[i][j][2 * h + 0] - BIAS64);
                o.y = 16.0f * (float)(int)(su[i][j][2 * h + 1] - BIAS64);
                *(float2*)(orow + 8 * j) = o;
            }
        }
#undef STAGE_ITER
}

// ---------------------------------------------------------------------------
extern "C" void kernel_launch(void* const* d_in, const int* in_sizes, int n_in,
                              void* d_out, int out_size) {
    const float* X    = (const float*)d_in[0];  // (2,1024,1024)
    const float* W    = (const float*)d_in[1];  // (1024,1024)
    const float* vmap = (const float*)d_in[2];  // (16,16)
    const float* wmap = (const float*)d_in[3];  // (16,16)
    float* out = (float*)d_out;                 // (2,1024,1024)

    cudaFuncSetAttribute(opu_main_kernel,
                         cudaFuncAttributeMaxDynamicSharedMemorySize, 2 * 49152);

    prep_kernel<<<768, 256>>>(X, W, vmap, wmap);
    opu_main_kernel<<<dim3(16, 16), 256, 2 * 49152>>>(out);
}

// round 8
// speedup vs baseline: 1.0390x; 1.0390x over previous
#include <cuda_runtime.h>
#include <cuda_fp16.h>
#include <cstdint>

#define K_DIM 1024
#define M_DIM 2048
#define N_DIM 1024
#define NCHUNK 64

// Operands stored in m16n8k16 fragment order.
// g_Ahi/g_Alo: [chunk][mfrag 0..127][lane 0..31] -> uint4 {a0a1,a2a3,a4a5,a6a7}
// g_B:         [chunk][nfrag 0..127][lane 0..31] -> uint4 {whi0,whi1,wlo0,wlo1}
__device__ uint4 g_Ahi[(size_t)NCHUNK * 128 * 32];
__device__ uint4 g_Alo[(size_t)NCHUNK * 128 * 32];
__device__ uint4 g_Bfr[(size_t)NCHUNK * 128 * 32];

// ---------------------------------------------------------------------------
// Fused prep: blocks [0,512) do X, [512,768) do W.
// Computes hi/lo fp16 split, then shuffles through smem into fragment layout.
// ---------------------------------------------------------------------------
__global__ void prep_kernel(const float* __restrict__ X,
                            const float* __restrict__ W,
                            const float* __restrict__ vmap,
                            const float* __restrict__ wmap) {
    __shared__ float s_lut[256];
    __shared__ unsigned sHi[256][9];   // pad 9 words: conflict-light
    __shared__ unsigned sLo[256][9];

    const int tid = threadIdx.x;
    const bool isX = blockIdx.x < 512;
    s_lut[tid] = isX ? vmap[tid] : wmap[tid];
    __syncthreads();

    unsigned hi[8], lo[8];
    if (isX) {
        const int b = blockIdx.x;
        const int r = b >> 3, m0b = (b & 7) * 256;
        const int m = m0b + tid;
        const float* src = X + (size_t)m * K_DIM + r * 16;
        float xs[16];
        ((float4*)xs)[0] = ((const float4*)src)[0];
        ((float4*)xs)[1] = ((const float4*)src)[1];
        ((float4*)xs)[2] = ((const float4*)src)[2];
        ((float4*)xs)[3] = ((const float4*)src)[3];
#pragma unroll
        for (int jj = 0; jj < 8; jj++) {
            unsigned short h[2], l[2];
#pragma unroll
            for (int e = 0; e < 2; e++) {
                int j = 2 * jj + e;
                float xv = xs[j];
                int idx = (int)(xv + 8.0f);
                idx = idx < 0 ? 0 : (idx > 15 ? 15 : idx);
                float xc = (xv + s_lut[j * 16 + idx]) * 0.0625f;
                __half hh = __float2half_rn(xc);
                __half ll = __float2half_rn(xc - __half2float(hh));
                h[e] = __half_as_ushort(hh);
                l[e] = __half_as_ushort(ll);
            }
            hi[jj] = h[0] | ((unsigned)h[1] << 16);
            lo[jj] = l[0] | ((unsigned)l[1] << 16);
        }
#pragma unroll
        for (int jj = 0; jj < 8; jj++) { sHi[tid][jj] = hi[jj]; sLo[tid][jj] = lo[jj]; }
        __syncthreads();

        // writeback in A fragment order: 512 hi + 512 lo segments, 2+2 per thread
#pragma unroll
        for (int ss = 0; ss < 2; ss++) {
            int s = tid + 256 * ss;
            int f = s >> 5, l = s & 31, g = l >> 2, tq = l & 3;
            int r0 = f * 16 + g, r1 = r0 + 8;
            uint4 H = make_uint4(sHi[r0][tq], sHi[r1][tq], sHi[r0][tq + 4], sHi[r1][tq + 4]);
            uint4 L = make_uint4(sLo[r0][tq], sLo[r1][tq], sLo[r0][tq + 4], sLo[r1][tq + 4]);
            size_t gi = ((size_t)r * 128 + (m0b >> 4) + f) * 32 + l;
            g_Ahi[gi] = H;
            g_Alo[gi] = L;
        }
    } else {
        const int b = blockIdx.x - 512;        // 0..255
        const int r = b >> 2, n0b = (b & 3) * 256;
        const int n = n0b + tid;
#pragma unroll
        for (int jj = 0; jj < 8; jj++) {
            unsigned short h[2], l[2];
#pragma unroll
            for (int e = 0; e < 2; e++) {
                int j = 2 * jj + e;
                float w = W[(size_t)(16 * r + j) * N_DIM + n];
                int idx = (int)(w + 8.0f);
                idx = idx < 0 ? 0 : (idx > 15 ? 15 : idx);
                float wc = w + s_lut[j * 16 + idx];
                __half hh = __float2half_rn(wc);
                __half ll = __float2half_rn(wc - __half2float(hh));
                h[e] = __half_as_ushort(hh);
                l[e] = __half_as_ushort(ll);
            }
            hi[jj] = h[0] | ((unsigned)h[1] << 16);
            lo[jj] = l[0] | ((unsigned)l[1] << 16);
        }
#pragma unroll
        for (int jj = 0; jj < 8; jj++) { sHi[tid][jj] = hi[jj]; sLo[tid][jj] = lo[jj]; }
        __syncthreads();

        // writeback in B fragment order: 32 frags x 32 lanes = 1024 segs, 4/thread
#pragma unroll
        for (int ss = 0; ss < 4; ss++) {
            int s = tid + 256 * ss;
            int f = s >> 5, l = s & 31, g = l >> 2, tq = l & 3;
            int nl = f * 8 + g;
            uint4 V = make_uint4(sHi[nl][tq], sHi[nl][tq + 4], sLo[nl][tq], sLo[nl][tq + 4]);
            g_Bfr[((size_t)r * 128 + (n0b >> 3) + f) * 32 + l] = V;
        }
    }
}

// ---------------------------------------------------------------------------
#define MMA_INIT(C, A, B0, B1, Z)                                              \
    asm("mma.sync.aligned.m16n8k16.row.col.f32.f16.f16.f32 "                   \
        "{%0,%1,%2,%3}, {%4,%5,%6,%7}, {%8,%9}, {%10,%10,%10,%10};"            \
        : "=f"((C)[0]), "=f"((C)[1]), "=f"((C)[2]), "=f"((C)[3])               \
        : "r"((A).x), "r"((A).y), "r"((A).z), "r"((A).w), "r"(B0), "r"(B1),    \
          "f"(Z))

#define MMA_ACC(C, A, B0, B1)                                                  \
    asm("mma.sync.aligned.m16n8k16.row.col.f32.f16.f16.f32 "                   \
        "{%0,%1,%2,%3}, {%4,%5,%6,%7}, {%8,%9}, {%0,%1,%2,%3};"                \
        : "+f"((C)[0]), "+f"((C)[1]), "+f"((C)[2]), "+f"((C)[3])               \
        : "r"((A).x), "r"((A).y), "r"((A).z), "r"((A).w), "r"(B0), "r"(B1))

// ---------------------------------------------------------------------------
// Main: no smem, no barriers. Each warp streams 64 chunks of fragments via
// LDG.128 (prefetch distance 1), 24 HMMA/chunk, per-chunk RNE + int accumulate.
// CTA tile 128m x 64n, 8 warps 4(m) x 2(n). grid (16,16), 2 CTA/SM.
// ---------------------------------------------------------------------------
__global__ void __launch_bounds__(256, 2)
opu_main_kernel(float* __restrict__ out) {
    const int t = threadIdx.x, wid = t >> 5, lane = t & 31;
    const int m0 = blockIdx.x * 128, n0 = blockIdx.y * 64;
    const int wm = (wid >> 1) * 32, wn = (wid & 1) * 32;

    const int mf = (m0 + wm) >> 4;   // global mfrag base (2 frags)
    const int nf = (n0 + wn) >> 3;   // global nfrag base (4 frags)

    const uint4* pA0 = g_Ahi + (size_t)mf * 32 + lane;
    const uint4* pA1 = g_Alo + (size_t)mf * 32 + lane;
    const uint4* pB  = g_Bfr + (size_t)nf * 32 + lane;
    const size_t CSTR = 128 * 32;    // uint4s per chunk

    unsigned su[2][4][4];
#pragma unroll
    for (int i = 0; i < 2; i++)
#pragma unroll
        for (int j = 0; j < 4; j++)
#pragma unroll
            for (int e = 0; e < 4; e++) su[i][j][e] = 0u;

    const float FZ = 0.0f;
    const float MAGIC = 12582912.0f;   // 1.5*2^23

    uint4 AH[2][2], AL[2][2], BF[2][4];

#define LOAD_CHUNK(buf, r)                                                     \
    do {                                                                       \
        const size_t o = (size_t)(r) * CSTR;                                   \
        AH[buf][0] = pA0[o];        AH[buf][1] = pA0[o + 32];                  \
        AL[buf][0] = pA1[o];        AL[buf][1] = pA1[o + 32];                  \
        BF[buf][0] = pB[o];         BF[buf][1] = pB[o + 32];                   \
        BF[buf][2] = pB[o + 64];    BF[buf][3] = pB[o + 96];                   \
    } while (0)

#define COMPUTE_CHUNK(buf)                                                     \
    do {                                                                       \
        _Pragma("unroll")                                                      \
        for (int i = 0; i < 2; i++) {                                          \
            _Pragma("unroll")                                                  \
            for (int jp = 0; jp < 2; jp++) {                                   \
                float a0[4], a1[4];                                            \
                const uint4 b0 = BF[buf][2 * jp], b1 = BF[buf][2 * jp + 1];    \
                MMA_INIT(a0, AH[buf][i], b0.x, b0.y, FZ);                      \
                MMA_INIT(a1, AH[buf][i], b1.x, b1.y, FZ);                      \
                MMA_ACC(a0, AH[buf][i], b0.z, b0.w);                           \
                MMA_ACC(a1, AH[buf][i], b1.z, b1.w);                           \
                MMA_ACC(a0, AL[buf][i], b0.x, b0.y);                           \
                MMA_ACC(a1, AL[buf][i], b1.x, b1.y);                           \
                _Pragma("unroll")                                              \
                for (int e = 0; e < 4; e++) {                                  \
                    su[i][2 * jp][e]     += __float_as_uint(a0[e] + MAGIC);    \
                    su[i][2 * jp + 1][e] += __float_as_uint(a1[e] + MAGIC);    \
                }                                                              \
            }                                                                  \
        }                                                                      \
    } while (0)

    LOAD_CHUNK(0, 0);
    for (int r = 0; r < NCHUNK; r += 2) {
        LOAD_CHUNK(1, r + 1);
        COMPUTE_CHUNK(0);
        int r2 = (r + 2 < NCHUNK) ? r + 2 : NCHUNK - 1;
        LOAD_CHUNK(0, r2);
        COMPUTE_CHUNK(1);
    }

    // out = 16 * (su - 64*0x4B400000 mod 2^32)
    const unsigned BIAS64 = 0xD0000000u;
    const int g = lane >> 2, tg = lane & 3;
#pragma unroll
    for (int i = 0; i < 2; i++)
#pragma unroll
        for (int h = 0; h < 2; h++) {
            int row = m0 + wm + 16 * i + 8 * h + g;
            float* orow = out + (size_t)row * N_DIM + n0 + wn + 2 * tg;
#pragma unroll
            for (int j = 0; j < 4; j++) {
                float2 o;
                o.x = 16.0f * (float)(int)(su[i][j][2 * h + 0] - BIAS64);
                o.y = 16.0f * (float)(int)(su[i][j][2 * h + 1] - BIAS64);
                *(float2*)(orow + 8 * j) = o;
            }
        }
#undef LOAD_CHUNK
#undef COMPUTE_CHUNK
}

// ---------------------------------------------------------------------------
extern "C" void kernel_launch(void* const* d_in, const int* in_sizes, int n_in,
                              void* d_out, int out_size) {
    const float* X    = (const float*)d_in[0];  // (2,1024,1024)
    const float* W    = (const float*)d_in[1];  // (1024,1024)
    const float* vmap = (const float*)d_in[2];  // (16,16)
    const float* wmap = (const float*)d_in[3];  // (16,16)
    float* out = (float*)d_out;                 // (2,1024,1024)

    prep_kernel<<<768, 256>>>(X, W, vmap, wmap);
    opu_main_kernel<<<dim3(16, 16), 256>>>(out);
}